// round 16
// baseline (speedup 1.0000x reference)
#include <cuda_runtime.h>
#include <cuda_fp16.h>
#include <math.h>
#include <stdint.h>

#define NN 50000
#define EE 1600000
#define IND 128
#define DD 64
#define G3 192
#define BN_EPS 1e-5f
#define SLOPE 0.2f

// ---------------- scratch (static __device__: no allocation) ----------------
__device__ float  g_h0[NN * DD];          // embed output (BN input)
__device__ float  g_pre[NN * DD];         // x @ lin_w + lin_b
__device__ float  g_h[NN * DD];
__device__ __half g_xth[NN * DD];
__device__ __half g_mh[NN * DD];          // aggregated messages (fp16)
__device__ float  g_adst[NN];
__device__ float  g_asrc[NN];
__device__ int    g_cnt[NN];
__device__ int    g_cnt8[8 * NN];
__device__ int    g_rowstart[NN];
__device__ int    g_cursor[NN];
__device__ int2   g_edge[EE];             // {src, __float_as_int(edge_bias)}
__device__ float  g_wihT[DD * G3];
__device__ float  g_whhT[DD * G3];
__device__ float  g_bnsum[DD];
__device__ float  g_bnsumsq[DD];

// ---------------- tf32 helpers ----------------
__device__ __forceinline__ unsigned f2tf(float x) {
    unsigned r;
    asm("cvt.rna.tf32.f32 %0, %1;" : "=r"(r) : "f"(x));
    return r;
}

__device__ __forceinline__ void mma_tf32(float c[4], const unsigned a[4],
                                         const unsigned b[2]) {
    asm volatile(
        "mma.sync.aligned.m16n8k8.row.col.f32.tf32.tf32.f32 "
        "{%0,%1,%2,%3}, {%4,%5,%6,%7}, {%8,%9}, {%0,%1,%2,%3};"
        : "+f"(c[0]), "+f"(c[1]), "+f"(c[2]), "+f"(c[3])
        : "r"(a[0]), "r"(a[1]), "r"(a[2]), "r"(a[3]),
          "r"(b[0]), "r"(b[1]));
}

__device__ __forceinline__ float sigf(float x) {
    return 1.f / (1.f + __expf(-x));
}

// 128-row-tile mainloop body (A stride 128 in smem)
__device__ __forceinline__ void panel_mma128(const unsigned* __restrict__ Asw,
                                             const unsigned* __restrict__ Ws,
                                             float acc[2][4][4],
                                             int warp_m, int warp_n, int rr, int kl)
{
#pragma unroll
    for (int ks = 0; ks < 8; ++ks) {
        const int kh0 = ks * 2;
        unsigned a[2][4];
#pragma unroll
        for (int mf = 0; mf < 2; ++mf) {
            int mb = warp_m * 32 + mf * 16 + rr;
            a[mf][0] = Asw[(kh0 * 128 + (mb ^ (kh0 & 7))) * 4 + kl];
            a[mf][1] = Asw[(kh0 * 128 + ((mb + 8) ^ (kh0 & 7))) * 4 + kl];
            a[mf][2] = Asw[((kh0 + 1) * 128 + (mb ^ ((kh0 + 1) & 7))) * 4 + kl];
            a[mf][3] = Asw[((kh0 + 1) * 128 + ((mb + 8) ^ ((kh0 + 1) & 7))) * 4 + kl];
        }
        unsigned b[4][2];
        const int kA = ks * 8 + kl;
        const int kB = kA + 4;
        const int swc = (kl << 3);
#pragma unroll
        for (int nf = 0; nf < 4; ++nf) {
            int n = warp_n * 32 + nf * 8 + rr;
            b[nf][0] = Ws[kA * 64 + (n ^ swc)];
            b[nf][1] = Ws[kB * 64 + (n ^ swc)];
        }
#pragma unroll
        for (int mf = 0; mf < 2; ++mf)
#pragma unroll
            for (int nf = 0; nf < 4; ++nf)
                mma_tf32(acc[mf][nf], a[mf], b[nf]);
    }
}

// weight panel: split load (LDG->regs) and store (cvt+STS) for pipelining
__device__ __forceinline__ void ws_ld(float4* pf, const float* __restrict__ W,
                                      int P, int c0, int t)
{
#pragma unroll
    for (int i = 0; i < 4; ++i) {
        int idx = t + 256 * i;
        int kk = idx >> 4;
        int n4 = (idx & 15) << 2;
        pf[i] = *(const float4*)(W + (size_t)kk * P + c0 + n4);
    }
}

__device__ __forceinline__ void ws_st(unsigned* Ws, const float4* pf, int t)
{
#pragma unroll
    for (int i = 0; i < 4; ++i) {
        int idx = t + 256 * i;
        int kk = idx >> 4;
        int n4 = (idx & 15) << 2;
        int nsw = n4 ^ ((kk & 3) << 3);
        Ws[kk * 64 + nsw + 0] = f2tf(pf[i].x);
        Ws[kk * 64 + nsw + 1] = f2tf(pf[i].y);
        Ws[kk * 64 + nsw + 2] = f2tf(pf[i].z);
        Ws[kk * 64 + nsw + 3] = f2tf(pf[i].w);
    }
}

__device__ __forceinline__ void load_wsP(unsigned* Ws, const float* __restrict__ W,
                                         int P, int c0, int t)
{
    float4 pf[4];
    ws_ld(pf, W, P, c0, t);
    ws_st(Ws, pf, t);
}

// xt half-store + fused attention-score epilogue (all 256 threads enter)
__device__ __forceinline__ void xt_attn_epilogue(
    float acc[2][4][4], const float* __restrict__ att_dst,
    const float* __restrict__ att_src, float* sred, __half* __restrict__ Ch,
    int n0, int n_rows, int warp_m, int warp_n, int lane)
{
    const int rr = lane >> 2, kl = lane & 3;

#pragma unroll
    for (int mf = 0; mf < 2; ++mf) {
        int row = n0 + warp_m * 32 + mf * 16 + rr;
#pragma unroll
        for (int nf = 0; nf < 4; ++nf) {
            int col = warp_n * 32 + nf * 8 + (lane & 3) * 2;
            if (row < n_rows)
                *(__half2*)(Ch + (size_t)row * 64 + col) =
                    __floats2half2_rn(acc[mf][nf][0], acc[mf][nf][1]);
            if (row + 8 < n_rows)
                *(__half2*)(Ch + (size_t)(row + 8) * 64 + col) =
                    __floats2half2_rn(acc[mf][nf][2], acc[mf][nf][3]);
        }
    }

    float vd[2][2] = {{0.f, 0.f}, {0.f, 0.f}};
    float vs[2][2] = {{0.f, 0.f}, {0.f, 0.f}};
#pragma unroll
    for (int nf = 0; nf < 4; ++nf) {
        int colb = warp_n * 32 + nf * 8 + (lane & 3) * 2;
        float d0 = att_dst[colb], d1 = att_dst[colb + 1];
        float s0v = att_src[colb], s1v = att_src[colb + 1];
#pragma unroll
        for (int mf = 0; mf < 2; ++mf)
#pragma unroll
            for (int hf = 0; hf < 2; ++hf) {
                float a0 = acc[mf][nf][hf * 2 + 0];
                float a1 = acc[mf][nf][hf * 2 + 1];
                vd[mf][hf] += a0 * d0 + a1 * d1;
                vs[mf][hf] += a0 * s0v + a1 * s1v;
            }
    }
#pragma unroll
    for (int o = 1; o <= 2; o <<= 1)
#pragma unroll
        for (int mf = 0; mf < 2; ++mf)
#pragma unroll
            for (int hf = 0; hf < 2; ++hf) {
                vd[mf][hf] += __shfl_xor_sync(0xffffffffu, vd[mf][hf], o);
                vs[mf][hf] += __shfl_xor_sync(0xffffffffu, vs[mf][hf], o);
            }

    __syncthreads();
    if (warp_n == 1 && kl == 0) {
#pragma unroll
        for (int mf = 0; mf < 2; ++mf)
#pragma unroll
            for (int hf = 0; hf < 2; ++hf) {
                int rl = warp_m * 32 + mf * 16 + hf * 8 + rr;
                sred[rl] = vd[mf][hf];
                sred[128 + rl] = vs[mf][hf];
            }
    }
    __syncthreads();
    if (warp_n == 0 && kl == 0) {
#pragma unroll
        for (int mf = 0; mf < 2; ++mf)
#pragma unroll
            for (int hf = 0; hf < 2; ++hf) {
                int rl = warp_m * 32 + mf * 16 + hf * 8 + rr;
                int row = n0 + rl;
                if (row < n_rows) {
                    g_adst[row] = vd[mf][hf] + sred[rl];
                    g_asrc[row] = vs[mf][hf] + sred[128 + rl];
                }
            }
    }
}

// ---- fused dual GEMM: h0 = x@mlp_w+mlp_b, pre = x@lin_w+lin_b, + BN stats --
__global__ void __launch_bounds__(256) gemm128_dual_kernel(
    const float* __restrict__ A,
    const float* __restrict__ W1, const float* __restrict__ b1,
    const float* __restrict__ W2, const float* __restrict__ b2,
    float* __restrict__ C1, float* __restrict__ C2, int n_rows)
{
    __shared__ uint4 As4[16 * 128];      // 32KB, aliased for stats in epilogue
    __shared__ unsigned Ws[64 * 64];     // 16KB  (48KB total)

    const int t    = threadIdx.x;
    const int lane = t & 31;
    const int wid  = t >> 5;
    const int warp_m = wid & 3;
    const int warp_n = wid >> 2;
    const int n0 = blockIdx.x * 128;

    float accE[2][4][4], accP[2][4][4];
#pragma unroll
    for (int mf = 0; mf < 2; ++mf)
#pragma unroll
        for (int nf = 0; nf < 4; ++nf)
#pragma unroll
            for (int r = 0; r < 4; ++r) { accE[mf][nf][r] = 0.f; accP[mf][nf][r] = 0.f; }

    const unsigned* Asw = reinterpret_cast<const unsigned*>(As4);
    const int rr = lane >> 2, kl = lane & 3;

    for (int k0 = 0; k0 < 128; k0 += 64) {
        __syncthreads();
#pragma unroll
        for (int i = 0; i < 8; ++i) {
            int idx = t + 256 * i;
            int m  = idx >> 4;
            int kh = idx & 15;
            int row = n0 + m;
            float4 v = make_float4(0.f, 0.f, 0.f, 0.f);
            if (row < n_rows)
                v = *(const float4*)(A + (size_t)row * 128 + k0 + kh * 4);
            As4[kh * 128 + (m ^ (kh & 7))] =
                make_uint4(f2tf(v.x), f2tf(v.y), f2tf(v.z), f2tf(v.w));
        }
        load_wsP(Ws, W1 + (size_t)k0 * 64, 64, 0, t);
        __syncthreads();
        panel_mma128(Asw, Ws, accE, warp_m, warp_n, rr, kl);
        __syncthreads();
        load_wsP(Ws, W2 + (size_t)k0 * 64, 64, 0, t);
        __syncthreads();
        panel_mma128(Asw, Ws, accP, warp_m, warp_n, rr, kl);
    }

    // epilogue: write h0/pre + column stats (smem aliased into dead A tile)
    __syncthreads();
    float* ssum = (float*)As4;           // [64]
    float* ssq  = ssum + 64;             // [64]
    if (t < 128) ssum[t] = 0.f;
    __syncthreads();

#pragma unroll
    for (int nf = 0; nf < 4; ++nf) {
        int colb = warp_n * 32 + nf * 8 + (lane & 3) * 2;
        float be0 = b1[colb], be1 = b1[colb + 1];
        float bp0 = b2[colb], bp1 = b2[colb + 1];
        float s0 = 0.f, q0 = 0.f, s1 = 0.f, q1 = 0.f;
#pragma unroll
        for (int mf = 0; mf < 2; ++mf)
#pragma unroll
            for (int hf = 0; hf < 2; ++hf) {
                int row = n0 + warp_m * 32 + mf * 16 + rr + hf * 8;
                float vE0 = accE[mf][nf][hf * 2 + 0] + be0;
                float vE1 = accE[mf][nf][hf * 2 + 1] + be1;
                if (row < n_rows) {
                    *(float2*)(C1 + (size_t)row * 64 + colb) =
                        make_float2(vE0, vE1);
                    *(float2*)(C2 + (size_t)row * 64 + colb) =
                        make_float2(accP[mf][nf][hf * 2 + 0] + bp0,
                                    accP[mf][nf][hf * 2 + 1] + bp1);
                    s0 += vE0; q0 += vE0 * vE0;
                    s1 += vE1; q1 += vE1 * vE1;
                }
            }
#pragma unroll
        for (int o = 4; o <= 16; o <<= 1) {
            s0 += __shfl_xor_sync(0xffffffffu, s0, o);
            q0 += __shfl_xor_sync(0xffffffffu, q0, o);
            s1 += __shfl_xor_sync(0xffffffffu, s1, o);
            q1 += __shfl_xor_sync(0xffffffffu, q1, o);
        }
        if (lane < 4) {
            atomicAdd(&ssum[colb], s0);
            atomicAdd(&ssq[colb],  q0);
            atomicAdd(&ssum[colb + 1], s1);
            atomicAdd(&ssq[colb + 1],  q1);
        }
    }
    __syncthreads();
    if (t < 64) {
        atomicAdd(&g_bnsum[t],   ssum[t]);
        atomicAdd(&g_bnsumsq[t], ssq[t]);
    }
}

// ---- step-0 conv GEMM with fused BN-apply on input + xt/attn epilogue ----
__global__ void __launch_bounds__(256) gemm64h_bn_attn_kernel(
    const float* __restrict__ W,
    const float* __restrict__ att_dst, const float* __restrict__ att_src,
    const float* __restrict__ bn_g, const float* __restrict__ bn_b,
    __half* __restrict__ Ch, int n_rows)
{
    __shared__ uint4 As4[16 * 128];
    __shared__ unsigned Ws[64 * 64];
    __shared__ float sscale[64], sshift[64];

    const int t    = threadIdx.x;
    const int lane = t & 31;
    const int wid  = t >> 5;
    const int warp_m = wid & 3;
    const int warp_n = wid >> 2;
    const int n0 = blockIdx.x * 128;

    if (t < 64) {
        const float invn = 1.f / (float)NN;
        float mu  = g_bnsum[t] * invn;
        float var = g_bnsumsq[t] * invn - mu * mu;
        float sc  = bn_g[t] * rsqrtf(var + BN_EPS);
        sscale[t] = sc;
        sshift[t] = fmaf(-mu, sc, bn_b[t]);
    }
    __syncthreads();

    const unsigned* Asw = reinterpret_cast<const unsigned*>(As4);
    const int rr = lane >> 2, kl = lane & 3;

#pragma unroll
    for (int i = 0; i < 8; ++i) {
        int idx = t + 256 * i;
        int m  = idx >> 4;
        int kh = idx & 15;
        int row = n0 + m;
        int c = kh * 4;
        float4 v = make_float4(0.f, 0.f, 0.f, 0.f);
        if (row < n_rows)
            v = *(const float4*)(g_h0 + (size_t)row * 64 + c);
        float o0 = fmaxf(fmaf(v.x, sscale[c + 0], sshift[c + 0]), 0.f);
        float o1 = fmaxf(fmaf(v.y, sscale[c + 1], sshift[c + 1]), 0.f);
        float o2 = fmaxf(fmaf(v.z, sscale[c + 2], sshift[c + 2]), 0.f);
        float o3 = fmaxf(fmaf(v.w, sscale[c + 3], sshift[c + 3]), 0.f);
        if (row < n_rows)
            *(float4*)(g_h + (size_t)row * 64 + c) = make_float4(o0, o1, o2, o3);
        As4[kh * 128 + (m ^ (kh & 7))] =
            make_uint4(f2tf(o0), f2tf(o1), f2tf(o2), f2tf(o3));
    }
    load_wsP(Ws, W, 64, 0, t);
    __syncthreads();

    float acc[2][4][4];
#pragma unroll
    for (int mf = 0; mf < 2; ++mf)
#pragma unroll
        for (int nf = 0; nf < 4; ++nf)
#pragma unroll
            for (int r = 0; r < 4; ++r) acc[mf][nf][r] = 0.f;

    panel_mma128(Asw, Ws, acc, warp_m, warp_n, rr, kl);

    xt_attn_epilogue(acc, att_dst, att_src, (float*)As4, Ch,
                     n0, n_rows, warp_m, warp_n, lane);
}

// ---------------- fused GRU (+ optional next-step conv), pipelined panels ---
// DO_CONV=false: final step; writes out = pre + h' directly (no g_h store).
template <bool DO_CONV>
__global__ void __launch_bounds__(256) gru_fused_kernel(
    const float* __restrict__ b_ih, const float* __restrict__ b_hh,
    const float* __restrict__ conv_w, const float* __restrict__ att_dst,
    const float* __restrict__ att_src, __half* __restrict__ Ch,
    const float* __restrict__ preb, float* __restrict__ outp, int n_rows)
{
    extern __shared__ char dsm[];
    uint4* Am4 = (uint4*)dsm;                       // 32KB (m tile / h' tile)
    uint4* Ah4 = (uint4*)(dsm + 32768);             // 32KB (h tile / scratch)
    unsigned* Ws0 = (unsigned*)(dsm + 65536);       // 16KB
    unsigned* Ws1 = (unsigned*)(dsm + 81920);       // 16KB

    const int t = threadIdx.x, lane = t & 31, wid = t >> 5;
    const int warp_m = wid & 3;
    const int warp_n = wid >> 2;
    const int n0 = blockIdx.x * 128;
    const int rr = lane >> 2, kl = lane & 3;
    const unsigned* Am = reinterpret_cast<const unsigned*>(Am4);
    const unsigned* Ah = reinterpret_cast<const unsigned*>(Ah4);

    float4 pf[4];
    ws_ld(pf, g_wihT, G3, 0, t);          // panel 0 in flight during staging

#pragma unroll
    for (int i = 0; i < 8; ++i) {
        int idx = t + 256 * i;
        int m  = idx >> 4;
        int kh = idx & 15;
        int row = n0 + m;
        float4 vh = make_float4(0.f, 0.f, 0.f, 0.f);
        float2 ma = make_float2(0.f, 0.f), mb = ma;
        if (row < n_rows) {
            vh = *(const float4*)(g_h + (size_t)row * 64 + kh * 4);
            uint2 mm = *(const uint2*)(g_mh + (size_t)row * 64 + kh * 4);
            ma = __half22float2(*(__half2*)&mm.x);
            mb = __half22float2(*(__half2*)&mm.y);
        }
        int s = kh * 128 + (m ^ (kh & 7));
        Am4[s] = make_uint4(f2tf(ma.x), f2tf(ma.y), f2tf(mb.x), f2tf(mb.y));
        Ah4[s] = make_uint4(f2tf(vh.x), f2tf(vh.y), f2tf(vh.z), f2tf(vh.w));
    }
    ws_st(Ws0, pf, t);
    __syncthreads();

    float accr[2][4][4], accn[2][4][4], acct[2][4][4];
#pragma unroll
    for (int mf = 0; mf < 2; ++mf)
#pragma unroll
        for (int nf = 0; nf < 4; ++nf)
#pragma unroll
            for (int q = 0; q < 4; ++q) {
                accr[mf][nf][q] = 0.f; accn[mf][nf][q] = 0.f; acct[mf][nf][q] = 0.f;
            }

    ws_ld(pf, g_whhT, G3, 0, t);
    panel_mma128(Am, Ws0, accr, warp_m, warp_n, rr, kl);
    ws_st(Ws1, pf, t); __syncthreads();

    ws_ld(pf, g_wihT, G3, 128, t);
    panel_mma128(Ah, Ws1, accr, warp_m, warp_n, rr, kl);
    ws_st(Ws0, pf, t); __syncthreads();

    ws_ld(pf, g_whhT, G3, 128, t);
    panel_mma128(Am, Ws0, accn, warp_m, warp_n, rr, kl);
    ws_st(Ws1, pf, t); __syncthreads();

    ws_ld(pf, g_wihT, G3, 64, t);
    panel_mma128(Ah, Ws1, acct, warp_m, warp_n, rr, kl);
    ws_st(Ws0, pf, t);

    // n = tanh(gi_n + r*gh_n)
#pragma unroll
    for (int mf = 0; mf < 2; ++mf)
#pragma unroll
        for (int nf = 0; nf < 4; ++nf) {
            int colb = warp_n * 32 + nf * 8 + (lane & 3) * 2;
#pragma unroll
            for (int q = 0; q < 4; ++q) {
                int col = colb + (q & 1);
                float r = sigf(accr[mf][nf][q] + b_ih[col] + b_hh[col]);
                accr[mf][nf][q] = tanhf(accn[mf][nf][q] + b_ih[128 + col] +
                                        r * (acct[mf][nf][q] + b_hh[128 + col]));
                accn[mf][nf][q] = 0.f;
            }
        }
    __syncthreads();

    ws_ld(pf, g_whhT, G3, 64, t);
    panel_mma128(Am, Ws0, accn, warp_m, warp_n, rr, kl);
    ws_st(Ws1, pf, t); __syncthreads();

    panel_mma128(Ah, Ws1, accn, warp_m, warp_n, rr, kl);

    // h' = (1-z)*n + z*h
#pragma unroll
    for (int mf = 0; mf < 2; ++mf) {
#pragma unroll
        for (int nf = 0; nf < 4; ++nf) {
            int colb = warp_n * 32 + nf * 8 + (lane & 3) * 2;
            float bz0 = b_ih[64 + colb] + b_hh[64 + colb];
            float bz1 = b_ih[64 + colb + 1] + b_hh[64 + colb + 1];
#pragma unroll
            for (int hf = 0; hf < 2; ++hf) {
                int row = n0 + warp_m * 32 + mf * 16 + rr + hf * 8;
                float2 h = make_float2(0.f, 0.f);
                if (row < n_rows)
                    h = *(const float2*)(g_h + (size_t)row * 64 + colb);
                float z0 = sigf(accn[mf][nf][hf * 2 + 0] + bz0);
                float z1 = sigf(accn[mf][nf][hf * 2 + 1] + bz1);
                float hn0 = (1.f - z0) * accr[mf][nf][hf * 2 + 0] + z0 * h.x;
                float hn1 = (1.f - z1) * accr[mf][nf][hf * 2 + 1] + z1 * h.y;
                if (DO_CONV) {
                    if (row < n_rows)
                        *(float2*)(g_h + (size_t)row * 64 + colb) =
                            make_float2(hn0, hn1);
                    accr[mf][nf][hf * 2 + 0] = hn0;
                    accr[mf][nf][hf * 2 + 1] = hn1;
                } else {
                    if (row < n_rows) {
                        float2 pre = *(const float2*)(preb + (size_t)row * 64 + colb);
                        *(float2*)(outp + (size_t)row * 64 + colb) =
                            make_float2(pre.x + hn0, pre.y + hn1);
                    }
                }
            }
        }
    }

    if (DO_CONV) {
        ws_ld(pf, conv_w, 64, 0, t);
        unsigned* Amw = (unsigned*)Am4;
        __syncthreads();   // all reads of Am (final mma done) before overwrite
#pragma unroll
        for (int mf = 0; mf < 2; ++mf)
#pragma unroll
            for (int nf = 0; nf < 4; ++nf)
#pragma unroll
                for (int q = 0; q < 4; ++q) {
                    int m  = warp_m * 32 + mf * 16 + (q >> 1) * 8 + rr;
                    int c  = warp_n * 32 + nf * 8 + (lane & 3) * 2 + (q & 1);
                    int kh = c >> 2;
                    Amw[(kh * 128 + (m ^ (kh & 7))) * 4 + (c & 3)] =
                        f2tf(accr[mf][nf][q]);
                }
        ws_st(Ws0, pf, t);
        __syncthreads();

        float acc[2][4][4];
#pragma unroll
        for (int mf = 0; mf < 2; ++mf)
#pragma unroll
            for (int nf = 0; nf < 4; ++nf)
#pragma unroll
                for (int r = 0; r < 4; ++r) acc[mf][nf][r] = 0.f;

        panel_mma128(Am, Ws0, acc, warp_m, warp_n, rr, kl);

        xt_attn_epilogue(acc, att_dst, att_src, (float*)Ah4, Ch,
                         n0, n_rows, warp_m, warp_n, lane);
    }
}

// ---------------- small kernels ----------------
__global__ void initA_kernel()
{
    int i = blockIdx.x * blockDim.x + threadIdx.x;
    int T = gridDim.x * blockDim.x;
    for (int k = i; k < 8 * NN; k += T) g_cnt8[k] = 0;
}

__global__ void initB_kernel(const float* __restrict__ wih,
                             const float* __restrict__ whh)
{
    int i = blockIdx.x * blockDim.x + threadIdx.x;
    int T = gridDim.x * blockDim.x;
    if (i < DD) { g_bnsum[i] = 0.f; g_bnsumsq[i] = 0.f; }
    for (int k = i; k < G3 * DD; k += T) {
        int j = k >> 6, c = k & 63;
        g_wihT[c * G3 + j] = wih[k];
        g_whhT[c * G3 + j] = whh[k];
    }
}

// 8-way split histogram (contention /8)
__global__ void hist_kernel(const int* __restrict__ eidx)
{
    const int4* d4 = (const int4*)(eidx + EE);
    int i = blockIdx.x * blockDim.x + threadIdx.x;
    int T = gridDim.x * blockDim.x;
    for (int e = i; e < EE / 4; e += T) {
        int4 v = d4[e];
        int* cnt = g_cnt8 + (e & 7) * NN;
        atomicAdd(&cnt[v.x], 1);
        atomicAdd(&cnt[v.y], 1);
        atomicAdd(&cnt[v.z], 1);
        atomicAdd(&cnt[v.w], 1);
    }
}

// coalesced shuffle-based block scan; sums the 8 histogram copies
__global__ void scan_kernel()
{
    __shared__ int warpsum[32];
    __shared__ int carry_s;
    int t = threadIdx.x;
    int lane = t & 31, wid = t >> 5;
    if (t == 0) carry_s = 0;
    __syncthreads();
    for (int base = 0; base < NN; base += 1024) {
        int i = base + t;
        int v = 0;
        if (i < NN) {
#pragma unroll
            for (int c = 0; c < 8; ++c) v += g_cnt8[c * NN + i];
        }
        int x = v;
#pragma unroll
        for (int o = 1; o < 32; o <<= 1) {
            int u = __shfl_up_sync(0xffffffffu, x, o);
            if (lane >= o) x += u;
        }
        if (lane == 31) warpsum[wid] = x;
        __syncthreads();
        if (wid == 0) {
            int w = warpsum[lane];
#pragma unroll
            for (int o = 1; o < 32; o <<= 1) {
                int u = __shfl_up_sync(0xffffffffu, w, o);
                if (lane >= o) w += u;
            }
            warpsum[lane] = w;
        }
        __syncthreads();
        int wprefix = (wid > 0) ? warpsum[wid - 1] : 0;
        int excl = carry_s + wprefix + x - v;
        if (i < NN) {
            g_cnt[i] = v;
            g_rowstart[i] = excl;
            g_cursor[i] = excl;
        }
        __syncthreads();
        if (t == 1023) carry_s += warpsum[31];
        __syncthreads();
    }
}

__global__ void scatter_kernel(const int* __restrict__ eidx,
                               const float* __restrict__ edge_attr,
                               const float* __restrict__ att_edge)
{
    float a0 = att_edge[0], a1 = att_edge[1], a2 = att_edge[2];
    const int4* s4 = (const int4*)eidx;
    const int4* d4 = (const int4*)(eidx + EE);
    const float4* ea4 = (const float4*)edge_attr;
    int i = blockIdx.x * blockDim.x + threadIdx.x;
    int T = gridDim.x * blockDim.x;
    for (int e = i; e < EE / 4; e += T) {
        int4 s = s4[e];
        int4 d = d4[e];
        float4 q0 = ea4[e * 3 + 0];
        float4 q1 = ea4[e * 3 + 1];
        float4 q2 = ea4[e * 3 + 2];
        float eb0 = q0.x * a0 + q0.y * a1 + q0.z * a2;
        float eb1 = q0.w * a0 + q1.x * a1 + q1.y * a2;
        float eb2 = q1.z * a0 + q1.w * a1 + q2.x * a2;
        float eb3 = q2.y * a0 + q2.z * a1 + q2.w * a2;
        g_edge[atomicAdd(&g_cursor[d.x], 1)] = make_int2(s.x, __float_as_int(eb0));
        g_edge[atomicAdd(&g_cursor[d.y], 1)] = make_int2(s.y, __float_as_int(eb1));
        g_edge[atomicAdd(&g_cursor[d.z], 1)] = make_int2(s.z, __float_as_int(eb2));
        g_edge[atomicAdd(&g_cursor[d.w], 1)] = make_int2(s.w, __float_as_int(eb3));
    }
}

// fused softmax + aggregation: single-pass exp, 8-wide half2 gather
__global__ void __launch_bounds__(256) attn_agg_kernel()
{
    __shared__ float slog[8 * 128];
    __shared__ int   ssi[8 * 128];

    int wslot = threadIdx.x >> 5;
    int n = blockIdx.x * 8 + wslot;
    int lane = threadIdx.x & 31;
    if (n >= NN) return;
    int deg = g_cnt[n], s0 = g_rowstart[n];
    float adst = g_adst[n];
    const __half2* xh2 = (const __half2*)g_xth;
    float* lw = slog + wslot * 128;
    int*   li = ssi + wslot * 128;
    float ax0 = 0.f, ay0 = 0.f, ax1 = 0.f, ay1 = 0.f, sum = 0.f;

    if (deg <= 128) {
        for (int j = lane; j < deg; j += 32) {
            int2 e = g_edge[s0 + j];
            float l = adst + g_asrc[e.x] + __int_as_float(e.y);
            l = l >= 0.f ? l : SLOPE * l;
            float ex = __expf(l);
            li[j] = e.x;
            lw[j] = ex;
            sum += ex;
        }
        __syncwarp();
        int j = 0;
        for (; j + 8 <= deg; j += 8) {
            float w0 = lw[j + 0], w1 = lw[j + 1], w2 = lw[j + 2], w3 = lw[j + 3];
            float w4 = lw[j + 4], w5 = lw[j + 5], w6 = lw[j + 6], w7 = lw[j + 7];
            float2 v0 = __half22float2(xh2[li[j + 0] * 32 + lane]);
            float2 v1 = __half22float2(xh2[li[j + 1] * 32 + lane]);
            float2 v2 = __half22float2(xh2[li[j + 2] * 32 + lane]);
            float2 v3 = __half22float2(xh2[li[j + 3] * 32 + lane]);
            float2 v4 = __half22float2(xh2[li[j + 4] * 32 + lane]);
            float2 v5 = __half22float2(xh2[li[j + 5] * 32 + lane]);
            float2 v6 = __half22float2(xh2[li[j + 6] * 32 + lane]);
            float2 v7 = __half22float2(xh2[li[j + 7] * 32 + lane]);
            ax0 += w0 * v0.x + w1 * v1.x + w2 * v2.x + w3 * v3.x;
            ay0 += w0 * v0.y + w1 * v1.y + w2 * v2.y + w3 * v3.y;
            ax1 += w4 * v4.x + w5 * v5.x + w6 * v6.x + w7 * v7.x;
            ay1 += w4 * v4.y + w5 * v5.y + w6 * v6.y + w7 * v7.y;
        }
        for (; j < deg; ++j) {
            float2 v = __half22float2(xh2[li[j] * 32 + lane]);
            ax0 += lw[j] * v.x; ay0 += lw[j] * v.y;
        }
    } else {
        for (int c0 = 0; c0 < deg; c0 += 128) {
            int cnt = deg - c0; if (cnt > 128) cnt = 128;
            __syncwarp();
#pragma unroll
            for (int u = 0; u < 4; ++u) {
                int sl = lane + 32 * u;
                int j = c0 + sl;
                if (sl < cnt) {
                    int2 e = g_edge[s0 + j];
                    float l = adst + g_asrc[e.x] + __int_as_float(e.y);
                    l = l >= 0.f ? l : SLOPE * l;
                    float ex = __expf(l);
                    sum += ex;
                    lw[sl] = ex;
                    li[sl] = e.x;
                }
            }
            __syncwarp();
            for (int j = 0; j < cnt; ++j) {
                float2 v = __half22float2(xh2[li[j] * 32 + lane]);
                ax0 += lw[j] * v.x; ay0 += lw[j] * v.y;
            }
        }
    }

    float ax = ax0 + ax1, ay = ay0 + ay1;
#pragma unroll
    for (int o = 16; o; o >>= 1)
        sum += __shfl_xor_sync(0xffffffffu, sum, o);
    float dinv = (deg > 0) ? 1.f / sum : 0.f;
    ((__half2*)g_mh)[(size_t)n * 32 + lane] =
        __floats2half2_rn(fmaxf(ax * dinv, 0.f), fmaxf(ay * dinv, 0.f));
}

// ---------------- launch ----------------
extern "C" void kernel_launch(void* const* d_in, const int* in_sizes, int n_in,
                              void* d_out, int out_size)
{
    const float* x        = (const float*)d_in[0];
    const float* edge_at  = (const float*)d_in[1];
    const float* mlp_w    = (const float*)d_in[2];
    const float* mlp_b    = (const float*)d_in[3];
    const float* bn_g     = (const float*)d_in[4];
    const float* bn_b     = (const float*)d_in[5];
    const float* conv_w   = (const float*)d_in[6];
    const float* att_dst  = (const float*)d_in[7];
    const float* att_src  = (const float*)d_in[8];
    const float* att_edge = (const float*)d_in[9];
    const float* w_ih     = (const float*)d_in[10];
    const float* w_hh     = (const float*)d_in[11];
    const float* b_ih     = (const float*)d_in[12];
    const float* b_hh     = (const float*)d_in[13];
    const float* lin_w    = (const float*)d_in[14];
    const float* lin_b    = (const float*)d_in[15];
    const int*   eidx     = (const int*)d_in[16];   // int32 (JAX x64 disabled)
    float* out = (float*)d_out;

    float *p_h0, *p_pre, *p_h;
    __half *p_xth;
    cudaGetSymbolAddress((void**)&p_h0,  g_h0);
    cudaGetSymbolAddress((void**)&p_pre, g_pre);
    cudaGetSymbolAddress((void**)&p_h,   g_h);
    cudaGetSymbolAddress((void**)&p_xth, g_xth);

    cudaFuncSetAttribute(gru_fused_kernel<true>,
                         cudaFuncAttributeMaxDynamicSharedMemorySize, 98304);
    cudaFuncSetAttribute(gru_fused_kernel<false>,
                         cudaFuncAttributeMaxDynamicSharedMemorySize, 98304);

    const int GB  = (NN + 127) / 128;   // 391
    const int WPB = (NN + 7) / 8;       // 6250

    // fork: edge-CSR chain on s2 runs concurrently with the dense chain
    cudaStream_t s2;
    cudaStreamCreateWithFlags(&s2, cudaStreamNonBlocking);
    cudaEvent_t evF, evJ;
    cudaEventCreateWithFlags(&evF, cudaEventDisableTiming);
    cudaEventCreateWithFlags(&evJ, cudaEventDisableTiming);
    cudaEventRecord(evF, 0);
    cudaStreamWaitEvent(s2, evF, 0);

    // branch A (s2): edge CSR build
    initA_kernel<<<128, 256, 0, s2>>>();
    hist_kernel<<<1024, 256, 0, s2>>>(eidx);
    scan_kernel<<<1, 1024, 0, s2>>>();
    scatter_kernel<<<1024, 256, 0, s2>>>(eidx, edge_at, att_edge);
    cudaEventRecord(evJ, s2);

    // branch B (default): fused embed+preout GEMM (with BN stats) then conv0
    initB_kernel<<<64, 256>>>(w_ih, w_hh);
    gemm128_dual_kernel<<<GB, 256>>>(x, mlp_w, mlp_b, lin_w, lin_b,
                                     p_h0, p_pre, NN);
    gemm64h_bn_attn_kernel<<<GB, 256>>>(conv_w, att_dst, att_src,
                                        bn_g, bn_b, p_xth, NN);

    // join
    cudaStreamWaitEvent(0, evJ, 0);

    // step 0
    attn_agg_kernel<<<WPB, 256>>>();
    gru_fused_kernel<true><<<GB, 256, 98304>>>(b_ih, b_hh, conv_w,
                                               att_dst, att_src, p_xth,
                                               nullptr, nullptr, NN);
    // step 1
    attn_agg_kernel<<<WPB, 256>>>();
    gru_fused_kernel<true><<<GB, 256, 98304>>>(b_ih, b_hh, conv_w,
                                               att_dst, att_src, p_xth,
                                               nullptr, nullptr, NN);
    // step 2: out = pre + h' written directly
    attn_agg_kernel<<<WPB, 256>>>();
    gru_fused_kernel<false><<<GB, 256, 98304>>>(b_ih, b_hh, nullptr,
                                                nullptr, nullptr, nullptr,
                                                p_pre, out, NN);
}

// round 17
// speedup vs baseline: 1.0430x; 1.0430x over previous
#include <cuda_runtime.h>
#include <cuda_fp16.h>
#include <math.h>
#include <stdint.h>

#define NN 50000
#define EE 1600000
#define IND 128
#define DD 64
#define G3 192
#define BN_EPS 1e-5f
#define SLOPE 0.2f

// ---------------- scratch (static __device__: no allocation) ----------------
__device__ float  g_h0[NN * DD];          // embed output, later pre-out
__device__ float  g_h[NN * DD];
__device__ __half g_xth[NN * DD];
__device__ __half g_mh[NN * DD];          // aggregated messages (fp16)
__device__ float  g_adst[NN];
__device__ float  g_asrc[NN];
__device__ int    g_cnt[NN];
__device__ int    g_cnt8[8 * NN];
__device__ int    g_rowstart[NN];
__device__ int    g_cursor[NN];
__device__ int2   g_edge[EE];             // {src, __float_as_int(edge_bias)}
__device__ float  g_wihT[DD * G3];
__device__ float  g_whhT[DD * G3];
__device__ float  g_bnsum[DD];
__device__ float  g_bnsumsq[DD];

// ---------------- tf32 helpers ----------------
__device__ __forceinline__ unsigned f2tf(float x) {
    unsigned r;
    asm("cvt.rna.tf32.f32 %0, %1;" : "=r"(r) : "f"(x));
    return r;
}

__device__ __forceinline__ void mma_tf32(float c[4], const unsigned a[4],
                                         const unsigned b[2]) {
    asm volatile(
        "mma.sync.aligned.m16n8k8.row.col.f32.tf32.tf32.f32 "
        "{%0,%1,%2,%3}, {%4,%5,%6,%7}, {%8,%9}, {%0,%1,%2,%3};"
        : "+f"(c[0]), "+f"(c[1]), "+f"(c[2]), "+f"(c[3])
        : "r"(a[0]), "r"(a[1]), "r"(a[2]), "r"(a[3]),
          "r"(b[0]), "r"(b[1]));
}

__device__ __forceinline__ float sigf(float x) {
    return 1.f / (1.f + __expf(-x));
}

// 128-row-tile mainloop body (A stride 128 in smem)
__device__ __forceinline__ void panel_mma128(const unsigned* __restrict__ Asw,
                                             const unsigned* __restrict__ Ws,
                                             float acc[2][4][4],
                                             int warp_m, int warp_n, int rr, int kl)
{
#pragma unroll
    for (int ks = 0; ks < 8; ++ks) {
        const int kh0 = ks * 2;
        unsigned a[2][4];
#pragma unroll
        for (int mf = 0; mf < 2; ++mf) {
            int mb = warp_m * 32 + mf * 16 + rr;
            a[mf][0] = Asw[(kh0 * 128 + (mb ^ (kh0 & 7))) * 4 + kl];
            a[mf][1] = Asw[(kh0 * 128 + ((mb + 8) ^ (kh0 & 7))) * 4 + kl];
            a[mf][2] = Asw[((kh0 + 1) * 128 + (mb ^ ((kh0 + 1) & 7))) * 4 + kl];
            a[mf][3] = Asw[((kh0 + 1) * 128 + ((mb + 8) ^ ((kh0 + 1) & 7))) * 4 + kl];
        }
        unsigned b[4][2];
        const int kA = ks * 8 + kl;
        const int kB = kA + 4;
        const int swc = (kl << 3);
#pragma unroll
        for (int nf = 0; nf < 4; ++nf) {
            int n = warp_n * 32 + nf * 8 + rr;
            b[nf][0] = Ws[kA * 64 + (n ^ swc)];
            b[nf][1] = Ws[kB * 64 + (n ^ swc)];
        }
#pragma unroll
        for (int mf = 0; mf < 2; ++mf)
#pragma unroll
            for (int nf = 0; nf < 4; ++nf)
                mma_tf32(acc[mf][nf], a[mf], b[nf]);
    }
}

// weight panel: split load (LDG->regs) and store (cvt+STS) for pipelining
__device__ __forceinline__ void ws_ld(float4* pf, const float* __restrict__ W,
                                      int P, int c0, int t)
{
#pragma unroll
    for (int i = 0; i < 4; ++i) {
        int idx = t + 256 * i;
        int kk = idx >> 4;
        int n4 = (idx & 15) << 2;
        pf[i] = *(const float4*)(W + (size_t)kk * P + c0 + n4);
    }
}

__device__ __forceinline__ void ws_st(unsigned* Ws, const float4* pf, int t)
{
#pragma unroll
    for (int i = 0; i < 4; ++i) {
        int idx = t + 256 * i;
        int kk = idx >> 4;
        int n4 = (idx & 15) << 2;
        int nsw = n4 ^ ((kk & 3) << 3);
        Ws[kk * 64 + nsw + 0] = f2tf(pf[i].x);
        Ws[kk * 64 + nsw + 1] = f2tf(pf[i].y);
        Ws[kk * 64 + nsw + 2] = f2tf(pf[i].z);
        Ws[kk * 64 + nsw + 3] = f2tf(pf[i].w);
    }
}

__device__ __forceinline__ void load_wsP(unsigned* Ws, const float* __restrict__ W,
                                         int P, int c0, int t)
{
    float4 pf[4];
    ws_ld(pf, W, P, c0, t);
    ws_st(Ws, pf, t);
}

// xt half-store + fused attention-score epilogue (all 256 threads enter)
__device__ __forceinline__ void xt_attn_epilogue(
    float acc[2][4][4], const float* __restrict__ att_dst,
    const float* __restrict__ att_src, float* sred, __half* __restrict__ Ch,
    int n0, int n_rows, int warp_m, int warp_n, int lane)
{
    const int rr = lane >> 2, kl = lane & 3;

#pragma unroll
    for (int mf = 0; mf < 2; ++mf) {
        int row = n0 + warp_m * 32 + mf * 16 + rr;
#pragma unroll
        for (int nf = 0; nf < 4; ++nf) {
            int col = warp_n * 32 + nf * 8 + (lane & 3) * 2;
            if (row < n_rows)
                *(__half2*)(Ch + (size_t)row * 64 + col) =
                    __floats2half2_rn(acc[mf][nf][0], acc[mf][nf][1]);
            if (row + 8 < n_rows)
                *(__half2*)(Ch + (size_t)(row + 8) * 64 + col) =
                    __floats2half2_rn(acc[mf][nf][2], acc[mf][nf][3]);
        }
    }

    float vd[2][2] = {{0.f, 0.f}, {0.f, 0.f}};
    float vs[2][2] = {{0.f, 0.f}, {0.f, 0.f}};
#pragma unroll
    for (int nf = 0; nf < 4; ++nf) {
        int colb = warp_n * 32 + nf * 8 + (lane & 3) * 2;
        float d0 = att_dst[colb], d1 = att_dst[colb + 1];
        float s0v = att_src[colb], s1v = att_src[colb + 1];
#pragma unroll
        for (int mf = 0; mf < 2; ++mf)
#pragma unroll
            for (int hf = 0; hf < 2; ++hf) {
                float a0 = acc[mf][nf][hf * 2 + 0];
                float a1 = acc[mf][nf][hf * 2 + 1];
                vd[mf][hf] += a0 * d0 + a1 * d1;
                vs[mf][hf] += a0 * s0v + a1 * s1v;
            }
    }
#pragma unroll
    for (int o = 1; o <= 2; o <<= 1)
#pragma unroll
        for (int mf = 0; mf < 2; ++mf)
#pragma unroll
            for (int hf = 0; hf < 2; ++hf) {
                vd[mf][hf] += __shfl_xor_sync(0xffffffffu, vd[mf][hf], o);
                vs[mf][hf] += __shfl_xor_sync(0xffffffffu, vs[mf][hf], o);
            }

    __syncthreads();
    if (warp_n == 1 && kl == 0) {
#pragma unroll
        for (int mf = 0; mf < 2; ++mf)
#pragma unroll
            for (int hf = 0; hf < 2; ++hf) {
                int rl = warp_m * 32 + mf * 16 + hf * 8 + rr;
                sred[rl] = vd[mf][hf];
                sred[128 + rl] = vs[mf][hf];
            }
    }
    __syncthreads();
    if (warp_n == 0 && kl == 0) {
#pragma unroll
        for (int mf = 0; mf < 2; ++mf)
#pragma unroll
            for (int hf = 0; hf < 2; ++hf) {
                int rl = warp_m * 32 + mf * 16 + hf * 8 + rr;
                int row = n0 + rl;
                if (row < n_rows) {
                    g_adst[row] = vd[mf][hf] + sred[rl];
                    g_asrc[row] = vs[mf][hf] + sred[128 + rl];
                }
            }
    }
}

// ---------------- tf32 GEMM, K=128 (embed w/ fused BN stats; preout plain) --
template <bool STATS>
__global__ void __launch_bounds__(256) gemm128_tf32_kernel(
    const float* __restrict__ A, const float* __restrict__ W,
    const float* __restrict__ bias, float* __restrict__ C, int n_rows, int P)
{
    __shared__ uint4 As4[16 * 128];
    __shared__ unsigned Ws[64 * 64];

    const int t    = threadIdx.x;
    const int lane = t & 31;
    const int wid  = t >> 5;
    const int warp_m = wid & 3;
    const int warp_n = wid >> 2;
    const int n0 = blockIdx.x * 128;
    const int c0 = blockIdx.y * 64;

    float acc[2][4][4];
#pragma unroll
    for (int mf = 0; mf < 2; ++mf)
#pragma unroll
        for (int nf = 0; nf < 4; ++nf)
#pragma unroll
            for (int r = 0; r < 4; ++r) acc[mf][nf][r] = 0.f;

    const unsigned* Asw = reinterpret_cast<const unsigned*>(As4);
    const int rr = lane >> 2, kl = lane & 3;

    for (int k0 = 0; k0 < 128; k0 += 64) {
        __syncthreads();
#pragma unroll
        for (int i = 0; i < 8; ++i) {
            int idx = t + 256 * i;
            int m  = idx >> 4;
            int kh = idx & 15;
            int row = n0 + m;
            float4 v = make_float4(0.f, 0.f, 0.f, 0.f);
            if (row < n_rows)
                v = *(const float4*)(A + (size_t)row * 128 + k0 + kh * 4);
            As4[kh * 128 + (m ^ (kh & 7))] =
                make_uint4(f2tf(v.x), f2tf(v.y), f2tf(v.z), f2tf(v.w));
        }
        load_wsP(Ws, W + (size_t)k0 * P, P, c0, t);
        __syncthreads();
        panel_mma128(Asw, Ws, acc, warp_m, warp_n, rr, kl);
    }

    if (!STATS) {
#pragma unroll
        for (int mf = 0; mf < 2; ++mf) {
            int row = n0 + warp_m * 32 + mf * 16 + rr;
#pragma unroll
            for (int nf = 0; nf < 4; ++nf) {
                int col = c0 + warp_n * 32 + nf * 8 + (lane & 3) * 2;
                float b0v = bias[col], b1v = bias[col + 1];
                if (row < n_rows)
                    *(float2*)(C + (size_t)row * P + col) =
                        make_float2(acc[mf][nf][0] + b0v, acc[mf][nf][1] + b1v);
                if (row + 8 < n_rows)
                    *(float2*)(C + (size_t)(row + 8) * P + col) =
                        make_float2(acc[mf][nf][2] + b0v, acc[mf][nf][3] + b1v);
            }
        }
    } else {
        // store + per-column BN stats (smem aliased into dead A tile)
        __syncthreads();
        float* ssum = (float*)As4;           // [64]
        float* ssq  = ssum + 64;             // [64]
        if (t < 128) ssum[t] = 0.f;
        __syncthreads();

#pragma unroll
        for (int nf = 0; nf < 4; ++nf) {
            int colb = warp_n * 32 + nf * 8 + (lane & 3) * 2;
            float b0v = bias[colb], b1v = bias[colb + 1];
            float s0 = 0.f, q0 = 0.f, s1 = 0.f, q1 = 0.f;
#pragma unroll
            for (int mf = 0; mf < 2; ++mf)
#pragma unroll
                for (int hf = 0; hf < 2; ++hf) {
                    int row = n0 + warp_m * 32 + mf * 16 + rr + hf * 8;
                    float v0 = acc[mf][nf][hf * 2 + 0] + b0v;
                    float v1 = acc[mf][nf][hf * 2 + 1] + b1v;
                    if (row < n_rows) {
                        *(float2*)(C + (size_t)row * 64 + colb) =
                            make_float2(v0, v1);
                        s0 += v0; q0 += v0 * v0;
                        s1 += v1; q1 += v1 * v1;
                    }
                }
#pragma unroll
            for (int o = 4; o <= 16; o <<= 1) {
                s0 += __shfl_xor_sync(0xffffffffu, s0, o);
                q0 += __shfl_xor_sync(0xffffffffu, q0, o);
                s1 += __shfl_xor_sync(0xffffffffu, s1, o);
                q1 += __shfl_xor_sync(0xffffffffu, q1, o);
            }
            if (lane < 4) {
                atomicAdd(&ssum[colb], s0);
                atomicAdd(&ssq[colb],  q0);
                atomicAdd(&ssum[colb + 1], s1);
                atomicAdd(&ssq[colb + 1],  q1);
            }
        }
        __syncthreads();
        if (t < 64) {
            atomicAdd(&g_bnsum[t],   ssum[t]);
            atomicAdd(&g_bnsumsq[t], ssq[t]);
        }
    }
}

// ---- step-0 conv GEMM with fused BN-apply on input + xt/attn epilogue ----
__global__ void __launch_bounds__(256) gemm64h_bn_attn_kernel(
    const float* __restrict__ W,
    const float* __restrict__ att_dst, const float* __restrict__ att_src,
    const float* __restrict__ bn_g, const float* __restrict__ bn_b,
    __half* __restrict__ Ch, int n_rows)
{
    __shared__ uint4 As4[16 * 128];
    __shared__ unsigned Ws[64 * 64];
    __shared__ float sscale[64], sshift[64];

    const int t    = threadIdx.x;
    const int lane = t & 31;
    const int wid  = t >> 5;
    const int warp_m = wid & 3;
    const int warp_n = wid >> 2;
    const int n0 = blockIdx.x * 128;

    if (t < 64) {
        const float invn = 1.f / (float)NN;
        float mu  = g_bnsum[t] * invn;
        float var = g_bnsumsq[t] * invn - mu * mu;
        float sc  = bn_g[t] * rsqrtf(var + BN_EPS);
        sscale[t] = sc;
        sshift[t] = fmaf(-mu, sc, bn_b[t]);
    }
    __syncthreads();

    const unsigned* Asw = reinterpret_cast<const unsigned*>(As4);
    const int rr = lane >> 2, kl = lane & 3;

#pragma unroll
    for (int i = 0; i < 8; ++i) {
        int idx = t + 256 * i;
        int m  = idx >> 4;
        int kh = idx & 15;
        int row = n0 + m;
        int c = kh * 4;
        float4 v = make_float4(0.f, 0.f, 0.f, 0.f);
        if (row < n_rows)
            v = *(const float4*)(g_h0 + (size_t)row * 64 + c);
        float o0 = fmaxf(fmaf(v.x, sscale[c + 0], sshift[c + 0]), 0.f);
        float o1 = fmaxf(fmaf(v.y, sscale[c + 1], sshift[c + 1]), 0.f);
        float o2 = fmaxf(fmaf(v.z, sscale[c + 2], sshift[c + 2]), 0.f);
        float o3 = fmaxf(fmaf(v.w, sscale[c + 3], sshift[c + 3]), 0.f);
        if (row < n_rows)
            *(float4*)(g_h + (size_t)row * 64 + c) = make_float4(o0, o1, o2, o3);
        As4[kh * 128 + (m ^ (kh & 7))] =
            make_uint4(f2tf(o0), f2tf(o1), f2tf(o2), f2tf(o3));
    }
    load_wsP(Ws, W, 64, 0, t);
    __syncthreads();

    float acc[2][4][4];
#pragma unroll
    for (int mf = 0; mf < 2; ++mf)
#pragma unroll
        for (int nf = 0; nf < 4; ++nf)
#pragma unroll
            for (int r = 0; r < 4; ++r) acc[mf][nf][r] = 0.f;

    panel_mma128(Asw, Ws, acc, warp_m, warp_n, rr, kl);

    xt_attn_epilogue(acc, att_dst, att_src, (float*)As4, Ch,
                     n0, n_rows, warp_m, warp_n, lane);
}

// ---------------- fused GRU (+ optional next-step conv), pipelined panels ---
// DO_CONV=false: final step; writes out = pre + h' directly (no g_h store).
template <bool DO_CONV>
__global__ void __launch_bounds__(256) gru_fused_kernel(
    const float* __restrict__ b_ih, const float* __restrict__ b_hh,
    const float* __restrict__ conv_w, const float* __restrict__ att_dst,
    const float* __restrict__ att_src, __half* __restrict__ Ch,
    const float* __restrict__ preb, float* __restrict__ outp, int n_rows)
{
    extern __shared__ char dsm[];
    uint4* Am4 = (uint4*)dsm;                       // 32KB (m tile / h' tile)
    uint4* Ah4 = (uint4*)(dsm + 32768);             // 32KB (h tile / scratch)
    unsigned* Ws0 = (unsigned*)(dsm + 65536);       // 16KB
    unsigned* Ws1 = (unsigned*)(dsm + 81920);       // 16KB

    const int t = threadIdx.x, lane = t & 31, wid = t >> 5;
    const int warp_m = wid & 3;
    const int warp_n = wid >> 2;
    const int n0 = blockIdx.x * 128;
    const int rr = lane >> 2, kl = lane & 3;
    const unsigned* Am = reinterpret_cast<const unsigned*>(Am4);
    const unsigned* Ah = reinterpret_cast<const unsigned*>(Ah4);

    float4 pf[4];
    ws_ld(pf, g_wihT, G3, 0, t);          // panel 0 in flight during staging

#pragma unroll
    for (int i = 0; i < 8; ++i) {
        int idx = t + 256 * i;
        int m  = idx >> 4;
        int kh = idx & 15;
        int row = n0 + m;
        float4 vh = make_float4(0.f, 0.f, 0.f, 0.f);
        float2 ma = make_float2(0.f, 0.f), mb = ma;
        if (row < n_rows) {
            vh = *(const float4*)(g_h + (size_t)row * 64 + kh * 4);
            uint2 mm = *(const uint2*)(g_mh + (size_t)row * 64 + kh * 4);
            ma = __half22float2(*(__half2*)&mm.x);
            mb = __half22float2(*(__half2*)&mm.y);
        }
        int s = kh * 128 + (m ^ (kh & 7));
        Am4[s] = make_uint4(f2tf(ma.x), f2tf(ma.y), f2tf(mb.x), f2tf(mb.y));
        Ah4[s] = make_uint4(f2tf(vh.x), f2tf(vh.y), f2tf(vh.z), f2tf(vh.w));
    }
    ws_st(Ws0, pf, t);
    __syncthreads();

    float accr[2][4][4], accn[2][4][4], acct[2][4][4];
#pragma unroll
    for (int mf = 0; mf < 2; ++mf)
#pragma unroll
        for (int nf = 0; nf < 4; ++nf)
#pragma unroll
            for (int q = 0; q < 4; ++q) {
                accr[mf][nf][q] = 0.f; accn[mf][nf][q] = 0.f; acct[mf][nf][q] = 0.f;
            }

    ws_ld(pf, g_whhT, G3, 0, t);
    panel_mma128(Am, Ws0, accr, warp_m, warp_n, rr, kl);
    ws_st(Ws1, pf, t); __syncthreads();

    ws_ld(pf, g_wihT, G3, 128, t);
    panel_mma128(Ah, Ws1, accr, warp_m, warp_n, rr, kl);
    ws_st(Ws0, pf, t); __syncthreads();

    ws_ld(pf, g_whhT, G3, 128, t);
    panel_mma128(Am, Ws0, accn, warp_m, warp_n, rr, kl);
    ws_st(Ws1, pf, t); __syncthreads();

    ws_ld(pf, g_wihT, G3, 64, t);
    panel_mma128(Ah, Ws1, acct, warp_m, warp_n, rr, kl);
    ws_st(Ws0, pf, t);

    // n = tanh(gi_n + r*gh_n)
#pragma unroll
    for (int mf = 0; mf < 2; ++mf)
#pragma unroll
        for (int nf = 0; nf < 4; ++nf) {
            int colb = warp_n * 32 + nf * 8 + (lane & 3) * 2;
#pragma unroll
            for (int q = 0; q < 4; ++q) {
                int col = colb + (q & 1);
                float r = sigf(accr[mf][nf][q] + b_ih[col] + b_hh[col]);
                accr[mf][nf][q] = tanhf(accn[mf][nf][q] + b_ih[128 + col] +
                                        r * (acct[mf][nf][q] + b_hh[128 + col]));
                accn[mf][nf][q] = 0.f;
            }
        }
    __syncthreads();

    ws_ld(pf, g_whhT, G3, 64, t);
    panel_mma128(Am, Ws0, accn, warp_m, warp_n, rr, kl);
    ws_st(Ws1, pf, t); __syncthreads();

    panel_mma128(Ah, Ws1, accn, warp_m, warp_n, rr, kl);

    // h' = (1-z)*n + z*h
#pragma unroll
    for (int mf = 0; mf < 2; ++mf) {
#pragma unroll
        for (int nf = 0; nf < 4; ++nf) {
            int colb = warp_n * 32 + nf * 8 + (lane & 3) * 2;
            float bz0 = b_ih[64 + colb] + b_hh[64 + colb];
            float bz1 = b_ih[64 + colb + 1] + b_hh[64 + colb + 1];
#pragma unroll
            for (int hf = 0; hf < 2; ++hf) {
                int row = n0 + warp_m * 32 + mf * 16 + rr + hf * 8;
                float2 h = make_float2(0.f, 0.f);
                if (row < n_rows)
                    h = *(const float2*)(g_h + (size_t)row * 64 + colb);
                float z0 = sigf(accn[mf][nf][hf * 2 + 0] + bz0);
                float z1 = sigf(accn[mf][nf][hf * 2 + 1] + bz1);
                float hn0 = (1.f - z0) * accr[mf][nf][hf * 2 + 0] + z0 * h.x;
                float hn1 = (1.f - z1) * accr[mf][nf][hf * 2 + 1] + z1 * h.y;
                if (DO_CONV) {
                    if (row < n_rows)
                        *(float2*)(g_h + (size_t)row * 64 + colb) =
                            make_float2(hn0, hn1);
                    accr[mf][nf][hf * 2 + 0] = hn0;
                    accr[mf][nf][hf * 2 + 1] = hn1;
                } else {
                    if (row < n_rows) {
                        float2 pre = *(const float2*)(preb + (size_t)row * 64 + colb);
                        *(float2*)(outp + (size_t)row * 64 + colb) =
                            make_float2(pre.x + hn0, pre.y + hn1);
                    }
                }
            }
        }
    }

    if (DO_CONV) {
        ws_ld(pf, conv_w, 64, 0, t);
        unsigned* Amw = (unsigned*)Am4;
        __syncthreads();   // all reads of Am (final mma done) before overwrite
#pragma unroll
        for (int mf = 0; mf < 2; ++mf)
#pragma unroll
            for (int nf = 0; nf < 4; ++nf)
#pragma unroll
                for (int q = 0; q < 4; ++q) {
                    int m  = warp_m * 32 + mf * 16 + (q >> 1) * 8 + rr;
                    int c  = warp_n * 32 + nf * 8 + (lane & 3) * 2 + (q & 1);
                    int kh = c >> 2;
                    Amw[(kh * 128 + (m ^ (kh & 7))) * 4 + (c & 3)] =
                        f2tf(accr[mf][nf][q]);
                }
        ws_st(Ws0, pf, t);
        __syncthreads();

        float acc[2][4][4];
#pragma unroll
        for (int mf = 0; mf < 2; ++mf)
#pragma unroll
            for (int nf = 0; nf < 4; ++nf)
#pragma unroll
                for (int r = 0; r < 4; ++r) acc[mf][nf][r] = 0.f;

        panel_mma128(Am, Ws0, acc, warp_m, warp_n, rr, kl);

        xt_attn_epilogue(acc, att_dst, att_src, (float*)Ah4, Ch,
                         n0, n_rows, warp_m, warp_n, lane);
    }
}

// ---------------- small kernels ----------------
__global__ void initA_kernel()
{
    int i = blockIdx.x * blockDim.x + threadIdx.x;
    int T = gridDim.x * blockDim.x;
    for (int k = i; k < 8 * NN; k += T) g_cnt8[k] = 0;
}

__global__ void initB_kernel(const float* __restrict__ wih,
                             const float* __restrict__ whh)
{
    int i = blockIdx.x * blockDim.x + threadIdx.x;
    int T = gridDim.x * blockDim.x;
    if (i < DD) { g_bnsum[i] = 0.f; g_bnsumsq[i] = 0.f; }
    for (int k = i; k < G3 * DD; k += T) {
        int j = k >> 6, c = k & 63;
        g_wihT[c * G3 + j] = wih[k];
        g_whhT[c * G3 + j] = whh[k];
    }
}

// 8-way split histogram (contention /8)
__global__ void hist_kernel(const int* __restrict__ eidx)
{
    const int4* d4 = (const int4*)(eidx + EE);
    int i = blockIdx.x * blockDim.x + threadIdx.x;
    int T = gridDim.x * blockDim.x;
    for (int e = i; e < EE / 4; e += T) {
        int4 v = d4[e];
        int* cnt = g_cnt8 + (e & 7) * NN;
        atomicAdd(&cnt[v.x], 1);
        atomicAdd(&cnt[v.y], 1);
        atomicAdd(&cnt[v.z], 1);
        atomicAdd(&cnt[v.w], 1);
    }
}

// coalesced shuffle-based block scan; sums the 8 histogram copies
__global__ void scan_kernel()
{
    __shared__ int warpsum[32];
    __shared__ int carry_s;
    int t = threadIdx.x;
    int lane = t & 31, wid = t >> 5;
    if (t == 0) carry_s = 0;
    __syncthreads();
    for (int base = 0; base < NN; base += 1024) {
        int i = base + t;
        int v = 0;
        if (i < NN) {
#pragma unroll
            for (int c = 0; c < 8; ++c) v += g_cnt8[c * NN + i];
        }
        int x = v;
#pragma unroll
        for (int o = 1; o < 32; o <<= 1) {
            int u = __shfl_up_sync(0xffffffffu, x, o);
            if (lane >= o) x += u;
        }
        if (lane == 31) warpsum[wid] = x;
        __syncthreads();
        if (wid == 0) {
            int w = warpsum[lane];
#pragma unroll
            for (int o = 1; o < 32; o <<= 1) {
                int u = __shfl_up_sync(0xffffffffu, w, o);
                if (lane >= o) w += u;
            }
            warpsum[lane] = w;
        }
        __syncthreads();
        int wprefix = (wid > 0) ? warpsum[wid - 1] : 0;
        int excl = carry_s + wprefix + x - v;
        if (i < NN) {
            g_cnt[i] = v;
            g_rowstart[i] = excl;
            g_cursor[i] = excl;
        }
        __syncthreads();
        if (t == 1023) carry_s += warpsum[31];
        __syncthreads();
    }
}

__global__ void scatter_kernel(const int* __restrict__ eidx,
                               const float* __restrict__ edge_attr,
                               const float* __restrict__ att_edge)
{
    float a0 = att_edge[0], a1 = att_edge[1], a2 = att_edge[2];
    const int4* s4 = (const int4*)eidx;
    const int4* d4 = (const int4*)(eidx + EE);
    const float4* ea4 = (const float4*)edge_attr;
    int i = blockIdx.x * blockDim.x + threadIdx.x;
    int T = gridDim.x * blockDim.x;
    for (int e = i; e < EE / 4; e += T) {
        int4 s = s4[e];
        int4 d = d4[e];
        float4 q0 = ea4[e * 3 + 0];
        float4 q1 = ea4[e * 3 + 1];
        float4 q2 = ea4[e * 3 + 2];
        float eb0 = q0.x * a0 + q0.y * a1 + q0.z * a2;
        float eb1 = q0.w * a0 + q1.x * a1 + q1.y * a2;
        float eb2 = q1.z * a0 + q1.w * a1 + q2.x * a2;
        float eb3 = q2.y * a0 + q2.z * a1 + q2.w * a2;
        g_edge[atomicAdd(&g_cursor[d.x], 1)] = make_int2(s.x, __float_as_int(eb0));
        g_edge[atomicAdd(&g_cursor[d.y], 1)] = make_int2(s.y, __float_as_int(eb1));
        g_edge[atomicAdd(&g_cursor[d.z], 1)] = make_int2(s.z, __float_as_int(eb2));
        g_edge[atomicAdd(&g_cursor[d.w], 1)] = make_int2(s.w, __float_as_int(eb3));
    }
}

// fused softmax + aggregation: single-pass exp, 8-wide half2 gather
__global__ void __launch_bounds__(256) attn_agg_kernel()
{
    __shared__ float slog[8 * 128];
    __shared__ int   ssi[8 * 128];

    int wslot = threadIdx.x >> 5;
    int n = blockIdx.x * 8 + wslot;
    int lane = threadIdx.x & 31;
    if (n >= NN) return;
    int deg = g_cnt[n], s0 = g_rowstart[n];
    float adst = g_adst[n];
    const __half2* xh2 = (const __half2*)g_xth;
    float* lw = slog + wslot * 128;
    int*   li = ssi + wslot * 128;
    float ax0 = 0.f, ay0 = 0.f, ax1 = 0.f, ay1 = 0.f, sum = 0.f;

    if (deg <= 128) {
        for (int j = lane; j < deg; j += 32) {
            int2 e = g_edge[s0 + j];
            float l = adst + g_asrc[e.x] + __int_as_float(e.y);
            l = l >= 0.f ? l : SLOPE * l;
            float ex = __expf(l);
            li[j] = e.x;
            lw[j] = ex;
            sum += ex;
        }
        __syncwarp();
        int j = 0;
        for (; j + 8 <= deg; j += 8) {
            float w0 = lw[j + 0], w1 = lw[j + 1], w2 = lw[j + 2], w3 = lw[j + 3];
            float w4 = lw[j + 4], w5 = lw[j + 5], w6 = lw[j + 6], w7 = lw[j + 7];
            float2 v0 = __half22float2(xh2[li[j + 0] * 32 + lane]);
            float2 v1 = __half22float2(xh2[li[j + 1] * 32 + lane]);
            float2 v2 = __half22float2(xh2[li[j + 2] * 32 + lane]);
            float2 v3 = __half22float2(xh2[li[j + 3] * 32 + lane]);
            float2 v4 = __half22float2(xh2[li[j + 4] * 32 + lane]);
            float2 v5 = __half22float2(xh2[li[j + 5] * 32 + lane]);
            float2 v6 = __half22float2(xh2[li[j + 6] * 32 + lane]);
            float2 v7 = __half22float2(xh2[li[j + 7] * 32 + lane]);
            ax0 += w0 * v0.x + w1 * v1.x + w2 * v2.x + w3 * v3.x;
            ay0 += w0 * v0.y + w1 * v1.y + w2 * v2.y + w3 * v3.y;
            ax1 += w4 * v4.x + w5 * v5.x + w6 * v6.x + w7 * v7.x;
            ay1 += w4 * v4.y + w5 * v5.y + w6 * v6.y + w7 * v7.y;
        }
        for (; j < deg; ++j) {
            float2 v = __half22float2(xh2[li[j] * 32 + lane]);
            ax0 += lw[j] * v.x; ay0 += lw[j] * v.y;
        }
    } else {
        for (int c0 = 0; c0 < deg; c0 += 128) {
            int cnt = deg - c0; if (cnt > 128) cnt = 128;
            __syncwarp();
#pragma unroll
            for (int u = 0; u < 4; ++u) {
                int sl = lane + 32 * u;
                int j = c0 + sl;
                if (sl < cnt) {
                    int2 e = g_edge[s0 + j];
                    float l = adst + g_asrc[e.x] + __int_as_float(e.y);
                    l = l >= 0.f ? l : SLOPE * l;
                    float ex = __expf(l);
                    sum += ex;
                    lw[sl] = ex;
                    li[sl] = e.x;
                }
            }
            __syncwarp();
            for (int j = 0; j < cnt; ++j) {
                float2 v = __half22float2(xh2[li[j] * 32 + lane]);
                ax0 += lw[j] * v.x; ay0 += lw[j] * v.y;
            }
        }
    }

    float ax = ax0 + ax1, ay = ay0 + ay1;
#pragma unroll
    for (int o = 16; o; o >>= 1)
        sum += __shfl_xor_sync(0xffffffffu, sum, o);
    float dinv = (deg > 0) ? 1.f / sum : 0.f;
    ((__half2*)g_mh)[(size_t)n * 32 + lane] =
        __floats2half2_rn(fmaxf(ax * dinv, 0.f), fmaxf(ay * dinv, 0.f));
}

// ---------------- launch ----------------
extern "C" void kernel_launch(void* const* d_in, const int* in_sizes, int n_in,
                              void* d_out, int out_size)
{
    const float* x        = (const float*)d_in[0];
    const float* edge_at  = (const float*)d_in[1];
    const float* mlp_w    = (const float*)d_in[2];
    const float* mlp_b    = (const float*)d_in[3];
    const float* bn_g     = (const float*)d_in[4];
    const float* bn_b     = (const float*)d_in[5];
    const float* conv_w   = (const float*)d_in[6];
    const float* att_dst  = (const float*)d_in[7];
    const float* att_src  = (const float*)d_in[8];
    const float* att_edge = (const float*)d_in[9];
    const float* w_ih     = (const float*)d_in[10];
    const float* w_hh     = (const float*)d_in[11];
    const float* b_ih     = (const float*)d_in[12];
    const float* b_hh     = (const float*)d_in[13];
    const float* lin_w    = (const float*)d_in[14];
    const float* lin_b    = (const float*)d_in[15];
    const int*   eidx     = (const int*)d_in[16];   // int32 (JAX x64 disabled)
    float* out = (float*)d_out;

    float *p_h0, *p_h;
    __half *p_xth;
    cudaGetSymbolAddress((void**)&p_h0,  g_h0);
    cudaGetSymbolAddress((void**)&p_h,   g_h);
    cudaGetSymbolAddress((void**)&p_xth, g_xth);

    cudaFuncSetAttribute(gru_fused_kernel<true>,
                         cudaFuncAttributeMaxDynamicSharedMemorySize, 98304);
    cudaFuncSetAttribute(gru_fused_kernel<false>,
                         cudaFuncAttributeMaxDynamicSharedMemorySize, 98304);

    const int GB  = (NN + 127) / 128;   // 391
    const int WPB = (NN + 7) / 8;       // 6250

    // fork: edge-CSR chain on s2 runs concurrently with the dense chain
    cudaStream_t s2;
    cudaStreamCreateWithFlags(&s2, cudaStreamNonBlocking);
    cudaEvent_t evF, evJ;
    cudaEventCreateWithFlags(&evF, cudaEventDisableTiming);
    cudaEventCreateWithFlags(&evJ, cudaEventDisableTiming);
    cudaEventRecord(evF, 0);
    cudaStreamWaitEvent(s2, evF, 0);

    // branch A (s2): edge CSR build
    initA_kernel<<<128, 256, 0, s2>>>();
    hist_kernel<<<1024, 256, 0, s2>>>(eidx);
    scan_kernel<<<1, 1024, 0, s2>>>();
    scatter_kernel<<<1024, 256, 0, s2>>>(eidx, edge_at, att_edge);
    cudaEventRecord(evJ, s2);

    // branch B (default): embed GEMM with fused BN stats, then conv0, preout
    initB_kernel<<<64, 256>>>(w_ih, w_hh);
    gemm128_tf32_kernel<true><<<dim3(GB, 1), 256>>>(x, mlp_w, mlp_b, p_h0, NN, DD);
    gemm64h_bn_attn_kernel<<<GB, 256>>>(conv_w, att_dst, att_src,
                                        bn_g, bn_b, p_xth, NN);
    // pre-out = x @ lin_w + lin_b (overwrites g_h0; its last read was above)
    gemm128_tf32_kernel<false><<<dim3(GB, 1), 256>>>(x, lin_w, lin_b, p_h0, NN, DD);

    // join
    cudaStreamWaitEvent(0, evJ, 0);

    // step 0
    attn_agg_kernel<<<WPB, 256>>>();
    gru_fused_kernel<true><<<GB, 256, 98304>>>(b_ih, b_hh, conv_w,
                                               att_dst, att_src, p_xth,
                                               nullptr, nullptr, NN);
    // step 1
    attn_agg_kernel<<<WPB, 256>>>();
    gru_fused_kernel<true><<<GB, 256, 98304>>>(b_ih, b_hh, conv_w,
                                               att_dst, att_src, p_xth,
                                               nullptr, nullptr, NN);
    // step 2: out = pre + h' written directly
    attn_agg_kernel<<<WPB, 256>>>();
    gru_fused_kernel<false><<<GB, 256, 98304>>>(b_ih, b_hh, nullptr,
                                                nullptr, nullptr, nullptr,
                                                p_h0, out, NN);
}